// round 8
// baseline (speedup 1.0000x reference)
#include <cuda_runtime.h>
#include <cuda_bf16.h>
#include <cstdint>

// Embedding gather: out[r, :] = table[indices[r], :]
// n_rows = B*F = 819200, D = 64 floats (256 B per row).
//
// R7: barrier-free double-buffered cp.async pipeline.
// Each thread cp.async-copies 4 x 16B chunks per tile into its OWN smem
// slots and reads them back itself -> only cp.async.wait_group needed,
// no __syncthreads. Two smem buffers let stores of tile t overlap the
// in-flight gathers of tile t+1: up to 8 outstanding gathers/thread
// (2048/block) at zero register cost, and a smooth read/write DRAM mix
// instead of per-block read-burst/write-burst phases.

static constexpr int D      = 64;            // embedding dim (floats)
static constexpr int LANES  = 16;            // float4 lanes per row
static constexpr int BLOCK  = 256;
static constexpr int TILE_ROWS = 64;                     // rows per tile
static constexpr int TILE_CHUNKS = TILE_ROWS * LANES;    // 1024 float4
static constexpr int CPT    = TILE_CHUNKS / BLOCK;       // 4 chunks/thread
static constexpr int NTILES = 4;                         // tiles per block
static constexpr int ROWS_PER_BLOCK = TILE_ROWS * NTILES;  // 256

__device__ __forceinline__ void cp16(uint32_t smem_dst, const float4* gsrc)
{
    asm volatile("cp.async.cg.shared.global [%0], [%1], 16;\n"
                 :: "r"(smem_dst), "l"(gsrc) : "memory");
}

__global__ __launch_bounds__(BLOCK)
void gather_kernel(const int* __restrict__ indices,
                   const float4* __restrict__ table4,
                   float4* __restrict__ out4,
                   unsigned n_rows)
{
    __shared__ float4 buf[2][TILE_CHUNKS];   // 2 x 16 KB

    const unsigned tid      = threadIdx.x;
    const unsigned row_base = blockIdx.x * (unsigned)ROWS_PER_BLOCK;

    // Thread-private chunk mapping: chunk c = tid + k*BLOCK
    //   row-in-tile = c>>4, lane = c&15. Loads and stores of a chunk are
    //   done by the SAME thread -> no cross-thread smem dependency.

    auto issue_tile = [&](int t) {
        const unsigned trow = row_base + (unsigned)t * TILE_ROWS;
        const uint32_t sb = (uint32_t)__cvta_generic_to_shared(buf[t & 1]);
#pragma unroll
        for (int k = 0; k < CPT; k++) {
            const unsigned c    = tid + (unsigned)k * BLOCK;
            const unsigned row  = trow + (c >> 4);
            const unsigned lane = c & 15u;
            const unsigned idx  = (row < n_rows) ? (unsigned)__ldg(indices + row) : 0u;
            cp16(sb + c * 16u, table4 + idx * (unsigned)(D / 4) + lane);
        }
        asm volatile("cp.async.commit_group;\n" ::: "memory");
    };

    auto store_tile = [&](int t) {
#pragma unroll
        for (int k = 0; k < CPT; k++) {
            const unsigned c   = tid + (unsigned)k * BLOCK;
            const unsigned row = row_base + (unsigned)t * TILE_ROWS + (c >> 4);
            if (row < n_rows)
                __stcs(out4 + row * (unsigned)(D / 4) + (c & 15u),
                       buf[t & 1][c]);
        }
    };

    issue_tile(0);
    issue_tile(1);
#pragma unroll
    for (int t = 0; t < NTILES - 2; t++) {
        asm volatile("cp.async.wait_group 1;\n" ::: "memory");  // tile t done
        store_tile(t);
        issue_tile(t + 2);
    }
    asm volatile("cp.async.wait_group 1;\n" ::: "memory");
    store_tile(NTILES - 2);
    asm volatile("cp.async.wait_group 0;\n" ::: "memory");
    store_tile(NTILES - 1);
}

extern "C" void kernel_launch(void* const* d_in, const int* in_sizes, int n_in,
                              void* d_out, int out_size)
{
    const int*    indices = (const int*)d_in[0];
    const float4* table4  = (const float4*)d_in[1];
    float4*       out4    = (float4*)d_out;

    const unsigned n_rows = (unsigned)in_sizes[0];   // 819200
    const unsigned grid   = (n_rows + ROWS_PER_BLOCK - 1) / ROWS_PER_BLOCK;  // 3200

    gather_kernel<<<grid, BLOCK>>>(indices, table4, out4, n_rows);
}

// round 9
// speedup vs baseline: 1.0187x; 1.0187x over previous
#include <cuda_runtime.h>
#include <cuda_bf16.h>
#include <cstdint>

// Embedding gather: out[r, :] = table[indices[r], :]
// n_rows = B*F = 819200, D = 64 floats (256 B per row).
//
// R8: converged structure (R6) + __ldcg for table gathers. Random gathers
// over a 256 MB footprint never hit L1; .cg bypasses L1 so each gather
// skips the L1 tag/wavefront path (L1 was at 42% for zero benefit).
// Everything else is the proven-best configuration: 16 float4 lanes/row,
// RPT=8 front-batched independent loads, u32 address math, exact-tile main
// kernel + guarded tail, .cs streaming stores.

static constexpr int D      = 64;           // embedding dim (floats)
static constexpr int LANES  = 16;           // float4 lanes per row
static constexpr int RPT    = 8;            // rows per thread
static constexpr int BLOCK  = 256;
static constexpr int ROWS_PER_BLOCK = (BLOCK / LANES) * RPT;  // 128

__global__ __launch_bounds__(BLOCK)
void gather_main(const int* __restrict__ indices,
                 const float4* __restrict__ table4,
                 float4* __restrict__ out4)
{
    const unsigned local_row = threadIdx.x >> 4;   // 0..15
    const unsigned lane      = threadIdx.x & 15u;  // 0..15
    const unsigned row_base  = blockIdx.x * (unsigned)ROWS_PER_BLOCK + local_row;

    unsigned idx[RPT];
    float4   vals[RPT];

    // Phase 1: batched independent index loads (L1-broadcast across lanes)
#pragma unroll
    for (int k = 0; k < RPT; k++)
        idx[k] = (unsigned)__ldg(indices + row_base + k * LANES);

    // Phase 2: batched independent table gathers, L1-bypass (L2 only)
#pragma unroll
    for (int k = 0; k < RPT; k++)
        vals[k] = __ldcg(table4 + idx[k] * (unsigned)(D / 4) + lane);

    // Phase 3: streaming stores (evict-first; output is write-once)
#pragma unroll
    for (int k = 0; k < RPT; k++)
        __stcs(out4 + (row_base + k * LANES) * (unsigned)(D / 4) + lane, vals[k]);
}

__global__ __launch_bounds__(BLOCK)
void gather_tail(const int* __restrict__ indices,
                 const float4* __restrict__ table4,
                 float4* __restrict__ out4,
                 unsigned row_start, unsigned n_rows)
{
    const unsigned row  = row_start + blockIdx.x * (BLOCK / LANES) + (threadIdx.x >> 4);
    const unsigned lane = threadIdx.x & 15u;
    if (row >= n_rows) return;
    const unsigned idx = (unsigned)__ldg(indices + row);
    __stcs(out4 + row * (unsigned)(D / 4) + lane,
           __ldcg(table4 + idx * (unsigned)(D / 4) + lane));
}

extern "C" void kernel_launch(void* const* d_in, const int* in_sizes, int n_in,
                              void* d_out, int out_size)
{
    const int*    indices = (const int*)d_in[0];
    const float4* table4  = (const float4*)d_in[1];
    float4*       out4    = (float4*)d_out;

    const unsigned n_rows    = (unsigned)in_sizes[0];          // 819200
    const unsigned full_blks = n_rows / ROWS_PER_BLOCK;        // 6400 (exact)
    const unsigned done      = full_blks * ROWS_PER_BLOCK;

    if (full_blks)
        gather_main<<<full_blks, BLOCK>>>(indices, table4, out4);

    if (done < n_rows) {
        const unsigned rem  = n_rows - done;
        const unsigned blks = (rem * LANES + BLOCK - 1) / BLOCK;
        gather_tail<<<blks, BLOCK>>>(indices, table4, out4, done, n_rows);
    }
}